// round 1
// baseline (speedup 1.0000x reference)
#include <cuda_runtime.h>
#include <math.h>

// Problem constants (fixed by the dataset)
#define NN   100000
#define EE   1600000
#define FH   128      // F_IN == HID
#define LATC 64

// ---------------------------------------------------------------------------
// Scratch (device globals; no allocation allowed)
// ---------------------------------------------------------------------------
__device__ int   g_is64;
__device__ int   g_src[EE];
__device__ int   g_dst[EE];
__device__ int   g_colsrc[EE];
__device__ int   g_rowptr[NN + 1];
__device__ int   g_cnt[NN];
__device__ int   g_bsums[128];
__device__ float g_Wcat[FH * 2 * FH];                 // packed [K, C1+C2]
__device__ float g_lin[(size_t)NN * 256];             // GEMM output (widest: 256)
__device__ float g_agg[(size_t)NN * FH];
__device__ float g_feat[(size_t)NN * FH];
__device__ float g_feat2[(size_t)NN * FH];
__device__ float g_als[NN];
__device__ float g_ald[NN];

// ---------------------------------------------------------------------------
// Helpers
// ---------------------------------------------------------------------------
__device__ __forceinline__ float lrelu02(float x) { return x > 0.f ? x : 0.2f * x; }

// ---------------------------------------------------------------------------
// Edge dtype detect + convert
// ---------------------------------------------------------------------------
__global__ void detect_k(const unsigned* __restrict__ w) {
    __shared__ unsigned red[256];
    unsigned v = 0;
    for (int i = threadIdx.x; i < 4096; i += 256) v |= w[2 * i + 1];
    red[threadIdx.x] = v;
    __syncthreads();
    for (int o = 128; o; o >>= 1) {
        if (threadIdx.x < o) red[threadIdx.x] |= red[threadIdx.x + o];
        __syncthreads();
    }
    if (threadIdx.x == 0) g_is64 = (red[0] == 0u) ? 1 : 0;
}

__global__ void convert_k(const void* __restrict__ edge) {
    int j = blockIdx.x * blockDim.x + threadIdx.x;
    if (j >= EE) return;
    if (g_is64) {
        const long long* p = (const long long*)edge;
        g_src[j] = (int)p[j];
        g_dst[j] = (int)p[(size_t)EE + j];
    } else {
        const int* p = (const int*)edge;
        g_src[j] = p[j];
        g_dst[j] = p[EE + j];
    }
}

// ---------------------------------------------------------------------------
// CSR build
// ---------------------------------------------------------------------------
__global__ void zero_cnt_k() {
    int i = blockIdx.x * blockDim.x + threadIdx.x;
    if (i < NN) g_cnt[i] = 0;
}

__global__ void count_k() {
    int j = blockIdx.x * blockDim.x + threadIdx.x;
    if (j < EE) atomicAdd(&g_cnt[g_dst[j]], 1);
}

__global__ void scan1_k() {   // per-block exclusive scan of g_cnt -> g_rowptr, block sums
    __shared__ int sm[1024];
    int t = threadIdx.x;
    int i = blockIdx.x * 1024 + t;
    int v = (i < NN) ? g_cnt[i] : 0;
    sm[t] = v;
    __syncthreads();
    for (int o = 1; o < 1024; o <<= 1) {
        int x = (t >= o) ? sm[t - o] : 0;
        __syncthreads();
        sm[t] += x;
        __syncthreads();
    }
    if (i < NN) g_rowptr[i] = sm[t] - v;     // exclusive
    if (t == 1023) g_bsums[blockIdx.x] = sm[t];
}

__global__ void scan2_k(int nb) {            // exclusive scan of block sums (nb <= 128)
    __shared__ int sm[128];
    int t = threadIdx.x;
    int v = (t < nb) ? g_bsums[t] : 0;
    sm[t] = v;
    __syncthreads();
    for (int o = 1; o < 128; o <<= 1) {
        int x = (t >= o) ? sm[t - o] : 0;
        __syncthreads();
        sm[t] += x;
        __syncthreads();
    }
    if (t < nb) g_bsums[t] = sm[t] - v;
}

__global__ void scan3_k() {
    int i = blockIdx.x * blockDim.x + threadIdx.x;
    if (i < NN) g_rowptr[i] += g_bsums[i >> 10];
    if (i == NN) g_rowptr[NN] = EE;
}

__global__ void fill_k() {
    int j = blockIdx.x * blockDim.x + threadIdx.x;
    if (j >= EE) return;
    int d = g_dst[j];
    int pos = g_rowptr[d] + atomicAdd(&g_cnt[d], 1);
    g_colsrc[pos] = g_src[j];
}

// ---------------------------------------------------------------------------
// Weight pack: Wcat = [W1 | W2] along columns
// ---------------------------------------------------------------------------
__global__ void pack2_k(const float* __restrict__ W1, int C1,
                        const float* __restrict__ W2, int C2, int K) {
    int i = blockIdx.x * blockDim.x + threadIdx.x;
    int Ct = C1 + C2;
    if (i >= K * Ct) return;
    int k = i / Ct, c = i % Ct;
    g_Wcat[i] = (c < C1) ? W1[k * C1 + c] : W2[k * C2 + (c - C1)];
}

// ---------------------------------------------------------------------------
// SGEMM: C[M,Ncol] = A[M,K] @ B[K,Ncol], fp32, 128x128 tile, 8x8 per thread
// K multiple of 16, Ncol multiple of 128.
// ---------------------------------------------------------------------------
__global__ __launch_bounds__(256)
void sgemm_k(const float* __restrict__ A, const float* __restrict__ B,
             float* __restrict__ C, int M, int Ncol, int K) {
    __shared__ float As[16][132];
    __shared__ float Bs[16][128];
    const int bm = blockIdx.x * 128;
    const int bn = blockIdx.y * 128;
    const int tid = threadIdx.x;
    const int tx = tid & 15;      // 0..15  (cols)
    const int ty = tid >> 4;      // 0..15  (rows)

    const int aRow0 = tid >> 2;          // 0..63
    const int aCol0 = (tid & 3) * 4;     // 0,4,8,12
    const int bRow0 = tid >> 5;          // 0..7
    const int bCol0 = (tid & 31) * 4;    // 0..124

    float acc[8][8];
#pragma unroll
    for (int i = 0; i < 8; i++)
#pragma unroll
        for (int j = 0; j < 8; j++) acc[i][j] = 0.f;

    for (int k0 = 0; k0 < K; k0 += 16) {
#pragma unroll
        for (int rr = 0; rr < 2; rr++) {
            int row = bm + aRow0 + rr * 64;
            float4 v = make_float4(0.f, 0.f, 0.f, 0.f);
            if (row < M) v = *(const float4*)(A + (size_t)row * K + k0 + aCol0);
            As[aCol0 + 0][aRow0 + rr * 64] = v.x;
            As[aCol0 + 1][aRow0 + rr * 64] = v.y;
            As[aCol0 + 2][aRow0 + rr * 64] = v.z;
            As[aCol0 + 3][aRow0 + rr * 64] = v.w;
        }
#pragma unroll
        for (int rr = 0; rr < 2; rr++) {
            int row = k0 + bRow0 + rr * 8;
            float4 v = *(const float4*)(B + (size_t)row * Ncol + bn + bCol0);
            *(float4*)&Bs[bRow0 + rr * 8][bCol0] = v;
        }
        __syncthreads();
#pragma unroll
        for (int kk = 0; kk < 16; kk++) {
            float4 a0 = *(const float4*)&As[kk][ty * 8];
            float4 a1 = *(const float4*)&As[kk][ty * 8 + 4];
            float4 b0 = *(const float4*)&Bs[kk][tx * 8];
            float4 b1 = *(const float4*)&Bs[kk][tx * 8 + 4];
            float ra[8] = {a0.x, a0.y, a0.z, a0.w, a1.x, a1.y, a1.z, a1.w};
            float rb[8] = {b0.x, b0.y, b0.z, b0.w, b1.x, b1.y, b1.z, b1.w};
#pragma unroll
            for (int i = 0; i < 8; i++)
#pragma unroll
                for (int j = 0; j < 8; j++) acc[i][j] = fmaf(ra[i], rb[j], acc[i][j]);
        }
        __syncthreads();
    }
#pragma unroll
    for (int i = 0; i < 8; i++) {
        int row = bm + ty * 8 + i;
        if (row < M) {
            float4 v0 = make_float4(acc[i][0], acc[i][1], acc[i][2], acc[i][3]);
            float4 v1 = make_float4(acc[i][4], acc[i][5], acc[i][6], acc[i][7]);
            *(float4*)(C + (size_t)row * Ncol + bn + tx * 8) = v0;
            *(float4*)(C + (size_t)row * Ncol + bn + tx * 8 + 4) = v1;
        }
    }
}

// ---------------------------------------------------------------------------
// Per-node attention logits: als[n] = h[n,:]·a_src, ald[n] = h[n,:]·a_dst
// ---------------------------------------------------------------------------
__global__ void al_k(const float* __restrict__ h, int ldh, int C,
                     const float* __restrict__ a_s, const float* __restrict__ a_d) {
    int w = (blockIdx.x * blockDim.x + threadIdx.x) >> 5;
    int lane = threadIdx.x & 31;
    if (w >= NN) return;
    const float* hp = h + (size_t)w * ldh;
    float ss = 0.f, dd = 0.f;
    for (int c = lane; c < C; c += 32) {
        float hv = hp[c];
        ss += hv * a_s[c];
        dd += hv * a_d[c];
    }
    for (int o = 16; o; o >>= 1) {
        ss += __shfl_xor_sync(0xffffffffu, ss, o);
        dd += __shfl_xor_sync(0xffffffffu, dd, o);
    }
    if (lane == 0) { g_als[w] = ss; g_ald[w] = dd; }
}

// ---------------------------------------------------------------------------
// GAT aggregation: warp per dst node; register softmax over incident edges.
// CH = channels per lane (4 -> C=128 via float4, 2 -> C=64 via float2)
// ---------------------------------------------------------------------------
template <int CH>
__global__ void gat_agg_k(const float* __restrict__ h, int ldh,
                          const float* __restrict__ bias,
                          float* __restrict__ out, int ldo, int addSelf) {
    int n = (blockIdx.x * blockDim.x + threadIdx.x) >> 5;
    int lane = threadIdx.x & 31;
    if (n >= NN) return;
    int beg = g_rowptr[n], end = g_rowptr[n + 1];
    float aldn = g_ald[n];

    // pass 1: segment max (lane-parallel)
    float m = -1e30f;
    for (int j = beg + lane; j < end; j += 32)
        m = fmaxf(m, lrelu02(g_als[g_colsrc[j]] + aldn));
    if (addSelf && lane == 0)
        m = fmaxf(m, lrelu02(g_als[n] + aldn));
    for (int o = 16; o; o >>= 1) m = fmaxf(m, __shfl_xor_sync(0xffffffffu, m, o));

    // pass 2: weighted accumulate (edges sequential, channels across lanes)
    float s = 0.f;
    float acc[CH];
#pragma unroll
    for (int i = 0; i < CH; i++) acc[i] = 0.f;

    for (int j = beg; j < end; ++j) {
        int sj = g_colsrc[j];
        float w = __expf(lrelu02(g_als[sj] + aldn) - m);
        s += w;
        const float* hp = h + (size_t)sj * ldh;
        if (CH == 4) {
            float4 v = *(const float4*)(hp + (lane << 2));
            acc[0] = fmaf(w, v.x, acc[0]); acc[1] = fmaf(w, v.y, acc[1]);
            acc[2] = fmaf(w, v.z, acc[2]); acc[3] = fmaf(w, v.w, acc[3]);
        } else {
            float2 v = *(const float2*)(hp + (lane << 1));
            acc[0] = fmaf(w, v.x, acc[0]); acc[1] = fmaf(w, v.y, acc[1]);
        }
    }
    if (addSelf) {
        float w = __expf(lrelu02(g_als[n] + aldn) - m);
        s += w;
        const float* hp = h + (size_t)n * ldh;
        if (CH == 4) {
            float4 v = *(const float4*)(hp + (lane << 2));
            acc[0] = fmaf(w, v.x, acc[0]); acc[1] = fmaf(w, v.y, acc[1]);
            acc[2] = fmaf(w, v.z, acc[2]); acc[3] = fmaf(w, v.w, acc[3]);
        } else {
            float2 v = *(const float2*)(hp + (lane << 1));
            acc[0] = fmaf(w, v.x, acc[0]); acc[1] = fmaf(w, v.y, acc[1]);
        }
    }

    float inv = 1.f / (s + 1e-16f);
    float* op = out + (size_t)n * ldo;
    if (CH == 4) {
        float4 r;
        r.x = acc[0] * inv; r.y = acc[1] * inv; r.z = acc[2] * inv; r.w = acc[3] * inv;
        if (bias) {
            const float4 b = *(const float4*)(bias + (lane << 2));
            r.x += b.x; r.y += b.y; r.z += b.z; r.w += b.w;
        }
        *(float4*)(op + (lane << 2)) = r;
    } else {
        float2 r;
        r.x = acc[0] * inv; r.y = acc[1] * inv;
        if (bias) {
            const float2 b = *(const float2*)(bias + (lane << 1));
            r.x += b.x; r.y += b.y;
        }
        *(float2*)(op + (lane << 1)) = r;
    }
}

// ---------------------------------------------------------------------------
// Combine: feat = LeakyReLU(agg + b + lin_self + slb, 0.01)
// lin row stride 256; self part at col offset 128.
// ---------------------------------------------------------------------------
__global__ void combine_k(const float* __restrict__ agg, const float* __restrict__ lin,
                          const float* __restrict__ b, const float* __restrict__ slb,
                          float* __restrict__ outf) {
    int i = blockIdx.x * blockDim.x + threadIdx.x;
    if (i >= NN * FH) return;
    int col = i & 127;
    int row = i >> 7;
    float v = agg[i] + b[col] + lin[(size_t)row * 256 + 128 + col] + slb[col];
    outf[i] = v > 0.f ? v : 0.01f * v;
}

// ---------------------------------------------------------------------------
// Launch
// ---------------------------------------------------------------------------
extern "C" void kernel_launch(void* const* d_in, const int* in_sizes, int n_in,
                              void* d_out, int out_size) {
    const float* x      = (const float*)d_in[0];
    const void*  edge   = d_in[1];
    const float* W0     = (const float*)d_in[2];
    const float* a_src0 = (const float*)d_in[3];
    const float* a_dst0 = (const float*)d_in[4];
    const float* b0     = (const float*)d_in[5];
    const float* slW0   = (const float*)d_in[6];
    const float* slb0   = (const float*)d_in[7];
    const float* W1     = (const float*)d_in[8];
    const float* a_src1 = (const float*)d_in[9];
    const float* a_dst1 = (const float*)d_in[10];
    const float* b1     = (const float*)d_in[11];
    const float* slW1   = (const float*)d_in[12];
    const float* slb1   = (const float*)d_in[13];
    const float* Wmu    = (const float*)d_in[14];
    const float* a_smu  = (const float*)d_in[15];
    const float* a_dmu  = (const float*)d_in[16];
    const float* b_mu   = (const float*)d_in[17];
    const float* Wlv    = (const float*)d_in[18];
    const float* a_slv  = (const float*)d_in[19];
    const float* a_dlv  = (const float*)d_in[20];
    const float* b_lv   = (const float*)d_in[21];
    float* out = (float*)d_out;

    // device-global pointers for kernels that take raw pointers
    float* lin;  cudaGetSymbolAddress((void**)&lin,  g_lin);
    float* agg;  cudaGetSymbolAddress((void**)&agg,  g_agg);
    float* feat; cudaGetSymbolAddress((void**)&feat, g_feat);
    float* feat2;cudaGetSymbolAddress((void**)&feat2,g_feat2);
    float* Wcat; cudaGetSymbolAddress((void**)&Wcat, g_Wcat);

    const int TB = 256;
    const int egrid = (EE + TB - 1) / TB;
    const int ngrid = (NN + TB - 1) / TB;
    const int nb = (NN + 1023) / 1024;
    const int warpsGrid = (NN * 32 + TB - 1) / TB;   // warp per node

    // --- edges -> int32 ---
    detect_k<<<1, 256>>>((const unsigned*)edge);
    convert_k<<<egrid, TB>>>(edge);

    // --- CSR by dst (no self loops) ---
    zero_cnt_k<<<ngrid, TB>>>();
    count_k<<<egrid, TB>>>();
    scan1_k<<<nb, 1024>>>();
    scan2_k<<<1, 128>>>(nb);
    scan3_k<<<(NN + 1 + TB - 1) / TB, TB>>>();
    zero_cnt_k<<<ngrid, TB>>>();
    fill_k<<<egrid, TB>>>();

    dim3 gemmBlk(256);

    // ===================== layer 0 =====================
    pack2_k<<<(FH * 256 + TB - 1) / TB, TB>>>(W0, FH, slW0, FH, FH);
    {
        dim3 grid((NN + 127) / 128, 2);
        sgemm_k<<<grid, gemmBlk>>>(x, Wcat, lin, NN, 256, FH);
    }
    al_k<<<warpsGrid, TB>>>(lin, 256, FH, a_src0, a_dst0);
    gat_agg_k<4><<<warpsGrid, TB>>>(lin, 256, nullptr, agg, FH, 0);
    combine_k<<<(NN * FH + TB - 1) / TB, TB>>>(agg, lin, b0, slb0, feat);

    // ===================== layer 1 =====================
    pack2_k<<<(FH * 256 + TB - 1) / TB, TB>>>(W1, FH, slW1, FH, FH);
    {
        dim3 grid((NN + 127) / 128, 2);
        sgemm_k<<<grid, gemmBlk>>>(feat, Wcat, lin, NN, 256, FH);
    }
    al_k<<<warpsGrid, TB>>>(lin, 256, FH, a_src1, a_dst1);
    gat_agg_k<4><<<warpsGrid, TB>>>(lin, 256, nullptr, agg, FH, 1);
    combine_k<<<(NN * FH + TB - 1) / TB, TB>>>(agg, lin, b1, slb1, feat2);

    // ===================== heads (mu | logvar) =====================
    pack2_k<<<(FH * 128 + TB - 1) / TB, TB>>>(Wmu, LATC, Wlv, LATC, FH);
    {
        dim3 grid((NN + 127) / 128, 1);
        sgemm_k<<<grid, gemmBlk>>>(feat2, Wcat, lin, NN, 128, FH);
    }
    // mu
    al_k<<<warpsGrid, TB>>>(lin, 128, LATC, a_smu, a_dmu);
    gat_agg_k<2><<<warpsGrid, TB>>>(lin, 128, b_mu, out, LATC, 1);
    // logvar
    al_k<<<warpsGrid, TB>>>(lin + 64, 128, LATC, a_slv, a_dlv);
    gat_agg_k<2><<<warpsGrid, TB>>>(lin + 64, 128, b_lv, out + (size_t)NN * LATC, LATC, 1);
}

// round 2
// speedup vs baseline: 1.3676x; 1.3676x over previous
#include <cuda_runtime.h>
#include <math.h>

// Problem constants (fixed by the dataset)
#define NN   100000
#define EE   1600000
#define FH   128      // F_IN == HID
#define LATC 64

// ---------------------------------------------------------------------------
// Scratch (device globals; no allocation allowed)
// ---------------------------------------------------------------------------
__device__ int   g_is64;
__device__ int   g_src[EE];
__device__ int   g_dst[EE];
__device__ int   g_colsrc[EE];
__device__ int   g_rowptr[NN + 1];
__device__ int   g_cnt[NN];
__device__ int   g_bsums[128];
__device__ float g_Wcat[FH * 2 * FH];                 // packed [K, C1+C2]
__device__ float g_lin[(size_t)NN * 256];             // GEMM output (widest: 256)
__device__ float g_feat[(size_t)NN * FH];
__device__ float g_feat2[(size_t)NN * FH];
__device__ float g_als[NN];
__device__ float g_ald[NN];
__device__ float g_als2[NN];
__device__ float g_ald2[NN];

__device__ __forceinline__ float lrelu02(float x) { return x > 0.f ? x : 0.2f * x; }

// ---------------------------------------------------------------------------
// Edge dtype detect + convert (+ degree count fused)
// ---------------------------------------------------------------------------
__global__ void detect_k(const unsigned* __restrict__ w) {
    __shared__ unsigned red[256];
    unsigned v = 0;
    for (int i = threadIdx.x; i < 4096; i += 256) v |= w[2 * i + 1];
    red[threadIdx.x] = v;
    __syncthreads();
    for (int o = 128; o; o >>= 1) {
        if (threadIdx.x < o) red[threadIdx.x] |= red[threadIdx.x + o];
        __syncthreads();
    }
    if (threadIdx.x == 0) g_is64 = (red[0] == 0u) ? 1 : 0;
}

__global__ void convert_count_k(const void* __restrict__ edge) {
    int j = blockIdx.x * blockDim.x + threadIdx.x;
    if (j >= EE) return;
    int s, d;
    if (g_is64) {
        const long long* p = (const long long*)edge;
        s = (int)p[j];
        d = (int)p[(size_t)EE + j];
    } else {
        const int* p = (const int*)edge;
        s = p[j];
        d = p[EE + j];
    }
    g_src[j] = s;
    g_dst[j] = d;
    atomicAdd(&g_cnt[d], 1);
}

// ---------------------------------------------------------------------------
// CSR build
// ---------------------------------------------------------------------------
__global__ void zero_cnt_k() {
    int i = blockIdx.x * blockDim.x + threadIdx.x;
    if (i < NN) g_cnt[i] = 0;
}

__global__ void scan1_k() {   // per-block exclusive scan of g_cnt -> g_rowptr
    __shared__ int sm[1024];
    int t = threadIdx.x;
    int i = blockIdx.x * 1024 + t;
    int v = (i < NN) ? g_cnt[i] : 0;
    sm[t] = v;
    __syncthreads();
    for (int o = 1; o < 1024; o <<= 1) {
        int x = (t >= o) ? sm[t - o] : 0;
        __syncthreads();
        sm[t] += x;
        __syncthreads();
    }
    if (i < NN) g_rowptr[i] = sm[t] - v;     // exclusive
    if (t == 1023) g_bsums[blockIdx.x] = sm[t];
}

__global__ void scan2_k(int nb) {            // exclusive scan of block sums
    __shared__ int sm[128];
    int t = threadIdx.x;
    int v = (t < nb) ? g_bsums[t] : 0;
    sm[t] = v;
    __syncthreads();
    for (int o = 1; o < 128; o <<= 1) {
        int x = (t >= o) ? sm[t - o] : 0;
        __syncthreads();
        sm[t] += x;
        __syncthreads();
    }
    if (t < nb) g_bsums[t] = sm[t] - v;
}

__global__ void scan3_k() {
    int i = blockIdx.x * blockDim.x + threadIdx.x;
    if (i < NN) g_rowptr[i] += g_bsums[i >> 10];
    if (i == NN) g_rowptr[NN] = EE;
}

__global__ void fill_k() {
    int j = blockIdx.x * blockDim.x + threadIdx.x;
    if (j >= EE) return;
    int d = g_dst[j];
    int pos = g_rowptr[d] + atomicAdd(&g_cnt[d], 1);
    g_colsrc[pos] = g_src[j];
}

// ---------------------------------------------------------------------------
// Weight pack: Wcat = [W1 | W2] along columns
// ---------------------------------------------------------------------------
__global__ void pack2_k(const float* __restrict__ W1, int C1,
                        const float* __restrict__ W2, int C2, int K) {
    int i = blockIdx.x * blockDim.x + threadIdx.x;
    int Ct = C1 + C2;
    if (i >= K * Ct) return;
    int k = i / Ct, c = i % Ct;
    g_Wcat[i] = (c < C1) ? W1[k * C1 + c] : W2[k * C2 + (c - C1)];
}

// ---------------------------------------------------------------------------
// 3xTF32 tensor-core GEMM: C[M,Ncol] = A[M,K] @ B[K,Ncol]
// CTA tile 128x128, BK=16, 8 warps (2x4), warp tile 64x32 (4x4 m16n8k8 frags).
// hi/lo tf32 split -> fp32-equivalent precision with 3 MMAs per product.
// ---------------------------------------------------------------------------
__device__ __forceinline__ void tf32split(float x, unsigned& hi, unsigned& lo) {
    unsigned h;
    asm("cvt.rna.tf32.f32 %0, %1;" : "=r"(h) : "f"(x));
    float hf = __uint_as_float(h);
    float r = x - hf;
    asm("cvt.rna.tf32.f32 %0, %1;" : "=r"(lo) : "f"(r));
    hi = h;
}

__device__ __forceinline__ void mma_tf32(float (&d)[4], const unsigned* a, const unsigned* b) {
    asm volatile(
        "mma.sync.aligned.m16n8k8.row.col.f32.tf32.tf32.f32 "
        "{%0,%1,%2,%3}, {%4,%5,%6,%7}, {%8,%9}, {%0,%1,%2,%3};"
        : "+f"(d[0]), "+f"(d[1]), "+f"(d[2]), "+f"(d[3])
        : "r"(a[0]), "r"(a[1]), "r"(a[2]), "r"(a[3]), "r"(b[0]), "r"(b[1]));
}

__global__ __launch_bounds__(256)
void gemm_tf32_k(const float* __restrict__ A, const float* __restrict__ B,
                 float* __restrict__ C, int M, int Ncol, int K) {
    __shared__ unsigned sAh[128][20], sAl[128][20];   // [row][k], pad 20
    __shared__ unsigned sBh[16][136], sBl[16][136];   // [k][n],  pad 136

    const int bm = blockIdx.x * 128;
    const int bn = blockIdx.y * 128;
    const int tid = threadIdx.x;
    const int lane = tid & 31;
    const int wid = tid >> 5;
    const int warpM = wid >> 2;     // 0..1 -> 64 rows
    const int warpN = wid & 3;      // 0..3 -> 32 cols

    float acc[4][4][4];
#pragma unroll
    for (int i = 0; i < 4; i++)
#pragma unroll
        for (int j = 0; j < 4; j++)
#pragma unroll
            for (int q = 0; q < 4; q++) acc[i][j][q] = 0.f;

    for (int k0 = 0; k0 < K; k0 += 16) {
        // --- load A chunk [128 x 16] ---
#pragma unroll
        for (int i = 0; i < 2; i++) {
            int f4 = tid + i * 256;
            int r = f4 >> 2, c4 = (f4 & 3) * 4;
            float4 v = make_float4(0.f, 0.f, 0.f, 0.f);
            if (bm + r < M) v = *(const float4*)(A + (size_t)(bm + r) * K + k0 + c4);
            unsigned h, l;
            tf32split(v.x, h, l); sAh[r][c4 + 0] = h; sAl[r][c4 + 0] = l;
            tf32split(v.y, h, l); sAh[r][c4 + 1] = h; sAl[r][c4 + 1] = l;
            tf32split(v.z, h, l); sAh[r][c4 + 2] = h; sAl[r][c4 + 2] = l;
            tf32split(v.w, h, l); sAh[r][c4 + 3] = h; sAl[r][c4 + 3] = l;
        }
        // --- load B chunk [16 x 128] ---
#pragma unroll
        for (int i = 0; i < 2; i++) {
            int f4 = tid + i * 256;
            int kr = f4 >> 5, n4 = (f4 & 31) * 4;
            float4 v = *(const float4*)(B + (size_t)(k0 + kr) * Ncol + bn + n4);
            unsigned h, l;
            tf32split(v.x, h, l); sBh[kr][n4 + 0] = h; sBl[kr][n4 + 0] = l;
            tf32split(v.y, h, l); sBh[kr][n4 + 1] = h; sBl[kr][n4 + 1] = l;
            tf32split(v.z, h, l); sBh[kr][n4 + 2] = h; sBl[kr][n4 + 2] = l;
            tf32split(v.w, h, l); sBh[kr][n4 + 3] = h; sBl[kr][n4 + 3] = l;
        }
        __syncthreads();

#pragma unroll
        for (int ks = 0; ks < 2; ks++) {
            const int kk = ks * 8 + (lane & 3);
            unsigned ah[4][4], al_[4][4], bh[4][2], bl[4][2];
#pragma unroll
            for (int mf = 0; mf < 4; mf++) {
                int r = warpM * 64 + mf * 16 + (lane >> 2);
                ah[mf][0] = sAh[r][kk];       al_[mf][0] = sAl[r][kk];
                ah[mf][1] = sAh[r + 8][kk];   al_[mf][1] = sAl[r + 8][kk];
                ah[mf][2] = sAh[r][kk + 4];   al_[mf][2] = sAl[r][kk + 4];
                ah[mf][3] = sAh[r + 8][kk + 4]; al_[mf][3] = sAl[r + 8][kk + 4];
            }
#pragma unroll
            for (int nf = 0; nf < 4; nf++) {
                int n = warpN * 32 + nf * 8 + (lane >> 2);
                bh[nf][0] = sBh[kk][n];     bl[nf][0] = sBl[kk][n];
                bh[nf][1] = sBh[kk + 4][n]; bl[nf][1] = sBl[kk + 4][n];
            }
#pragma unroll
            for (int mf = 0; mf < 4; mf++)
#pragma unroll
                for (int nf = 0; nf < 4; nf++) {
                    mma_tf32(acc[mf][nf], al_[mf], bh[nf]);
                    mma_tf32(acc[mf][nf], ah[mf], bl[nf]);
                    mma_tf32(acc[mf][nf], ah[mf], bh[nf]);
                }
        }
        __syncthreads();
    }

    // --- epilogue ---
#pragma unroll
    for (int mf = 0; mf < 4; mf++) {
        int r0 = bm + warpM * 64 + mf * 16 + (lane >> 2);
#pragma unroll
        for (int nf = 0; nf < 4; nf++) {
            int c = bn + warpN * 32 + nf * 8 + 2 * (lane & 3);
            if (r0 < M)
                *(float2*)(C + (size_t)r0 * Ncol + c) = make_float2(acc[mf][nf][0], acc[mf][nf][1]);
            if (r0 + 8 < M)
                *(float2*)(C + (size_t)(r0 + 8) * Ncol + c) = make_float2(acc[mf][nf][2], acc[mf][nf][3]);
        }
    }
}

// ---------------------------------------------------------------------------
// Per-node attention logits, C=128 (float4 per lane)
// ---------------------------------------------------------------------------
__global__ void al128_k(const float* __restrict__ h, int ldh,
                        const float* __restrict__ a_s, const float* __restrict__ a_d) {
    int n = (blockIdx.x * blockDim.x + threadIdx.x) >> 5;
    int lane = threadIdx.x & 31;
    if (n >= NN) return;
    float4 v = *(const float4*)(h + (size_t)n * ldh + lane * 4);
    float4 as4 = *(const float4*)(a_s + lane * 4);
    float4 ad4 = *(const float4*)(a_d + lane * 4);
    float ss = v.x * as4.x + v.y * as4.y + v.z * as4.z + v.w * as4.w;
    float dd = v.x * ad4.x + v.y * ad4.y + v.z * ad4.z + v.w * ad4.w;
    for (int o = 16; o; o >>= 1) {
        ss += __shfl_xor_sync(0xffffffffu, ss, o);
        dd += __shfl_xor_sync(0xffffffffu, dd, o);
    }
    if (lane == 0) { g_als[n] = ss; g_ald[n] = dd; }
}

// Heads: 4 dots at once. mu uses cols 0..63, lv uses cols 64..127 of lin (ld 128).
__global__ void al_heads_k(const float* __restrict__ h,
                           const float* __restrict__ a_smu, const float* __restrict__ a_dmu,
                           const float* __restrict__ a_slv, const float* __restrict__ a_dlv) {
    int n = (blockIdx.x * blockDim.x + threadIdx.x) >> 5;
    int lane = threadIdx.x & 31;
    if (n >= NN) return;
    float4 v = *(const float4*)(h + (size_t)n * 128 + lane * 4);
    float4 as4, ad4;
    if (lane < 16) {
        as4 = *(const float4*)(a_smu + lane * 4);
        ad4 = *(const float4*)(a_dmu + lane * 4);
    } else {
        as4 = *(const float4*)(a_slv + (lane - 16) * 4);
        ad4 = *(const float4*)(a_dlv + (lane - 16) * 4);
    }
    float ss = v.x * as4.x + v.y * as4.y + v.z * as4.z + v.w * as4.w;
    float dd = v.x * ad4.x + v.y * ad4.y + v.z * ad4.z + v.w * ad4.w;
    for (int o = 8; o; o >>= 1) {   // reduce within each 16-lane half
        ss += __shfl_xor_sync(0xffffffffu, ss, o);
        dd += __shfl_xor_sync(0xffffffffu, dd, o);
    }
    if (lane == 0)  { g_als[n]  = ss; g_ald[n]  = dd; }
    if (lane == 16) { g_als2[n] = ss; g_ald2[n] = dd; }
}

// ---------------------------------------------------------------------------
// Layer aggregation + fused combine:
// feat[n] = LeakyReLU( softmax-agg(h_gat) + b + h_self + slb, 0.01 )
// h layout: [N,256], gat part cols 0..127, self-linear cols 128..255.
// ---------------------------------------------------------------------------
__global__ void agg_layer_k(const float* __restrict__ h,
                            const float* __restrict__ b, const float* __restrict__ slb,
                            float* __restrict__ outf, int addSelf) {
    int n = (blockIdx.x * blockDim.x + threadIdx.x) >> 5;
    int lane = threadIdx.x & 31;
    if (n >= NN) return;
    int beg = g_rowptr[n], end = g_rowptr[n + 1];
    float aldn = g_ald[n];

    float m = addSelf ? lrelu02(g_als[n] + aldn) : -1e30f;
    for (int j = beg + lane; j < end; j += 32)
        m = fmaxf(m, lrelu02(g_als[g_colsrc[j]] + aldn));
    for (int o = 16; o; o >>= 1) m = fmaxf(m, __shfl_xor_sync(0xffffffffu, m, o));

    float s = 0.f;
    float a0 = 0.f, a1 = 0.f, a2 = 0.f, a3 = 0.f;
    const int co = lane << 2;
    for (int j = beg; j < end; ++j) {
        int sj = g_colsrc[j];
        float w = __expf(lrelu02(g_als[sj] + aldn) - m);
        s += w;
        float4 v = *(const float4*)(h + (size_t)sj * 256 + co);
        a0 = fmaf(w, v.x, a0); a1 = fmaf(w, v.y, a1);
        a2 = fmaf(w, v.z, a2); a3 = fmaf(w, v.w, a3);
    }
    if (addSelf) {
        float w = __expf(lrelu02(g_als[n] + aldn) - m);
        s += w;
        float4 v = *(const float4*)(h + (size_t)n * 256 + co);
        a0 = fmaf(w, v.x, a0); a1 = fmaf(w, v.y, a1);
        a2 = fmaf(w, v.z, a2); a3 = fmaf(w, v.w, a3);
    }
    float inv = 1.f / (s + 1e-16f);
    float4 bb  = *(const float4*)(b + co);
    float4 sb  = *(const float4*)(slb + co);
    float4 sl  = *(const float4*)(h + (size_t)n * 256 + 128 + co);
    float4 r;
    r.x = a0 * inv + bb.x + sl.x + sb.x;
    r.y = a1 * inv + bb.y + sl.y + sb.y;
    r.z = a2 * inv + bb.z + sl.z + sb.z;
    r.w = a3 * inv + bb.w + sl.w + sb.w;
    r.x = r.x > 0.f ? r.x : 0.01f * r.x;
    r.y = r.y > 0.f ? r.y : 0.01f * r.y;
    r.z = r.z > 0.f ? r.z : 0.01f * r.z;
    r.w = r.w > 0.f ? r.w : 0.01f * r.w;
    *(float4*)(outf + (size_t)n * 128 + co) = r;
}

// ---------------------------------------------------------------------------
// Heads aggregation (mu + logvar in one pass). h: [N,128] (mu cols 0..63, lv 64..127).
// Lanes 0..15 -> mu channels, 16..31 -> lv. Self loops always on.
// ---------------------------------------------------------------------------
__global__ void agg_heads_k(const float* __restrict__ h,
                            const float* __restrict__ b_mu, const float* __restrict__ b_lv,
                            float* __restrict__ out) {
    int n = (blockIdx.x * blockDim.x + threadIdx.x) >> 5;
    int lane = threadIdx.x & 31;
    if (n >= NN) return;
    int beg = g_rowptr[n], end = g_rowptr[n + 1];
    float aldmu = g_ald[n], aldlv = g_ald2[n];

    float mmu = lrelu02(g_als[n] + aldmu);     // self term
    float mlv = lrelu02(g_als2[n] + aldlv);
    for (int j = beg + lane; j < end; j += 32) {
        int sj = g_colsrc[j];
        mmu = fmaxf(mmu, lrelu02(g_als[sj] + aldmu));
        mlv = fmaxf(mlv, lrelu02(g_als2[sj] + aldlv));
    }
    for (int o = 16; o; o >>= 1) {
        mmu = fmaxf(mmu, __shfl_xor_sync(0xffffffffu, mmu, o));
        mlv = fmaxf(mlv, __shfl_xor_sync(0xffffffffu, mlv, o));
    }
    const bool isMu = lane < 16;
    const float msel = isMu ? mmu : mlv;

    float s = 0.f;
    float a0 = 0.f, a1 = 0.f, a2 = 0.f, a3 = 0.f;
    const int co = lane << 2;
    for (int j = beg; j < end; ++j) {
        int sj = g_colsrc[j];
        float e = isMu ? lrelu02(g_als[sj] + aldmu) : lrelu02(g_als2[sj] + aldlv);
        float w = __expf(e - msel);
        s += w;
        float4 v = *(const float4*)(h + (size_t)sj * 128 + co);
        a0 = fmaf(w, v.x, a0); a1 = fmaf(w, v.y, a1);
        a2 = fmaf(w, v.z, a2); a3 = fmaf(w, v.w, a3);
    }
    {   // self loop
        float e = isMu ? lrelu02(g_als[n] + aldmu) : lrelu02(g_als2[n] + aldlv);
        float w = __expf(e - msel);
        s += w;
        float4 v = *(const float4*)(h + (size_t)n * 128 + co);
        a0 = fmaf(w, v.x, a0); a1 = fmaf(w, v.y, a1);
        a2 = fmaf(w, v.z, a2); a3 = fmaf(w, v.w, a3);
    }
    float inv = 1.f / (s + 1e-16f);
    if (isMu) {
        float4 bb = *(const float4*)(b_mu + co);
        float4 r = make_float4(a0 * inv + bb.x, a1 * inv + bb.y,
                               a2 * inv + bb.z, a3 * inv + bb.w);
        *(float4*)(out + (size_t)n * 64 + co) = r;
    } else {
        int c2 = (lane - 16) << 2;
        float4 bb = *(const float4*)(b_lv + c2);
        float4 r = make_float4(a0 * inv + bb.x, a1 * inv + bb.y,
                               a2 * inv + bb.z, a3 * inv + bb.w);
        *(float4*)(out + (size_t)NN * 64 + (size_t)n * 64 + c2) = r;
    }
}

// ---------------------------------------------------------------------------
// Launch
// ---------------------------------------------------------------------------
extern "C" void kernel_launch(void* const* d_in, const int* in_sizes, int n_in,
                              void* d_out, int out_size) {
    const float* x      = (const float*)d_in[0];
    const void*  edge   = d_in[1];
    const float* W0     = (const float*)d_in[2];
    const float* a_src0 = (const float*)d_in[3];
    const float* a_dst0 = (const float*)d_in[4];
    const float* b0     = (const float*)d_in[5];
    const float* slW0   = (const float*)d_in[6];
    const float* slb0   = (const float*)d_in[7];
    const float* W1     = (const float*)d_in[8];
    const float* a_src1 = (const float*)d_in[9];
    const float* a_dst1 = (const float*)d_in[10];
    const float* b1     = (const float*)d_in[11];
    const float* slW1   = (const float*)d_in[12];
    const float* slb1   = (const float*)d_in[13];
    const float* Wmu    = (const float*)d_in[14];
    const float* a_smu  = (const float*)d_in[15];
    const float* a_dmu  = (const float*)d_in[16];
    const float* b_mu   = (const float*)d_in[17];
    const float* Wlv    = (const float*)d_in[18];
    const float* a_slv  = (const float*)d_in[19];
    const float* a_dlv  = (const float*)d_in[20];
    const float* b_lv   = (const float*)d_in[21];
    float* out = (float*)d_out;

    float* lin;  cudaGetSymbolAddress((void**)&lin,  g_lin);
    float* feat; cudaGetSymbolAddress((void**)&feat, g_feat);
    float* feat2;cudaGetSymbolAddress((void**)&feat2,g_feat2);
    float* Wcat; cudaGetSymbolAddress((void**)&Wcat, g_Wcat);

    const int TB = 256;
    const int egrid = (EE + TB - 1) / TB;
    const int ngrid = (NN + TB - 1) / TB;
    const int nb = (NN + 1023) / 1024;
    const int warpsGrid = (NN * 32 + TB - 1) / TB;   // warp per node

    // --- edges -> int32, degree count, CSR ---
    zero_cnt_k<<<ngrid, TB>>>();
    detect_k<<<1, 256>>>((const unsigned*)edge);
    convert_count_k<<<egrid, TB>>>(edge);
    scan1_k<<<nb, 1024>>>();
    scan2_k<<<1, 128>>>(nb);
    scan3_k<<<(NN + 1 + TB - 1) / TB, TB>>>();
    zero_cnt_k<<<ngrid, TB>>>();
    fill_k<<<egrid, TB>>>();

    // ===================== layer 0 =====================
    pack2_k<<<(FH * 256 + TB - 1) / TB, TB>>>(W0, FH, slW0, FH, FH);
    {
        dim3 grid((NN + 127) / 128, 2);
        gemm_tf32_k<<<grid, 256>>>(x, Wcat, lin, NN, 256, FH);
    }
    al128_k<<<warpsGrid, TB>>>(lin, 256, a_src0, a_dst0);
    agg_layer_k<<<warpsGrid, TB>>>(lin, b0, slb0, feat, 0);

    // ===================== layer 1 =====================
    pack2_k<<<(FH * 256 + TB - 1) / TB, TB>>>(W1, FH, slW1, FH, FH);
    {
        dim3 grid((NN + 127) / 128, 2);
        gemm_tf32_k<<<grid, 256>>>(feat, Wcat, lin, NN, 256, FH);
    }
    al128_k<<<warpsGrid, TB>>>(lin, 256, a_src1, a_dst1);
    agg_layer_k<<<warpsGrid, TB>>>(lin, b1, slb1, feat2, 1);

    // ===================== heads (mu | logvar) =====================
    pack2_k<<<(FH * 128 + TB - 1) / TB, TB>>>(Wmu, LATC, Wlv, LATC, FH);
    {
        dim3 grid((NN + 127) / 128, 1);
        gemm_tf32_k<<<grid, 256>>>(feat2, Wcat, lin, NN, 128, FH);
    }
    al_heads_k<<<warpsGrid, TB>>>(lin, a_smu, a_dmu, a_slv, a_dlv);
    agg_heads_k<<<warpsGrid, TB>>>(lin, b_mu, b_lv, out);
}

// round 3
// speedup vs baseline: 1.5298x; 1.1186x over previous
#include <cuda_runtime.h>
#include <cuda_bf16.h>
#include <math.h>

// Problem constants (fixed by the dataset)
#define NN   100000
#define EE   1600000
#define FH   128      // F_IN == HID
#define LATC 64
#define GK   128      // GEMM K (always 128)

// ---------------------------------------------------------------------------
// Scratch (device globals; no allocation allowed)
// ---------------------------------------------------------------------------
__device__ int   g_is64;
__device__ int   g_src[EE];
__device__ int   g_dst[EE];
__device__ int   g_colsrc[EE];
__device__ int   g_rowptr[NN + 1];
__device__ int   g_cnt[NN];
__device__ int   g_bsums[128];
__device__ float g_Wcat[FH * 2 * FH];                 // packed [K, C1+C2]
__device__ float g_lin[(size_t)NN * 256];             // GEMM output (widest: 256)
__device__ float g_feat[(size_t)NN * FH];
__device__ float g_feat2[(size_t)NN * FH];
__device__ float g_als[NN];
__device__ float g_ald[NN];
__device__ float g_als2[NN];
__device__ float g_ald2[NN];

__device__ __forceinline__ float lrelu02(float x) { return x > 0.f ? x : 0.2f * x; }

// ---------------------------------------------------------------------------
// Edge dtype detect + convert (+ degree count fused)
// ---------------------------------------------------------------------------
__global__ void detect_k(const unsigned* __restrict__ w) {
    __shared__ unsigned red[256];
    unsigned v = 0;
    for (int i = threadIdx.x; i < 4096; i += 256) v |= w[2 * i + 1];
    red[threadIdx.x] = v;
    __syncthreads();
    for (int o = 128; o; o >>= 1) {
        if (threadIdx.x < o) red[threadIdx.x] |= red[threadIdx.x + o];
        __syncthreads();
    }
    if (threadIdx.x == 0) g_is64 = (red[0] == 0u) ? 1 : 0;
}

__global__ void convert_count_k(const void* __restrict__ edge) {
    int j = blockIdx.x * blockDim.x + threadIdx.x;
    if (j >= EE) return;
    int s, d;
    if (g_is64) {
        const long long* p = (const long long*)edge;
        s = (int)p[j];
        d = (int)p[(size_t)EE + j];
    } else {
        const int* p = (const int*)edge;
        s = p[j];
        d = p[EE + j];
    }
    g_src[j] = s;
    g_dst[j] = d;
    atomicAdd(&g_cnt[d], 1);
}

// ---------------------------------------------------------------------------
// CSR build
// ---------------------------------------------------------------------------
__global__ void zero_cnt_k() {
    int i = blockIdx.x * blockDim.x + threadIdx.x;
    if (i < NN) g_cnt[i] = 0;
}

__global__ void scan1_k() {   // per-block exclusive scan of g_cnt -> g_rowptr
    __shared__ int sm[1024];
    int t = threadIdx.x;
    int i = blockIdx.x * 1024 + t;
    int v = (i < NN) ? g_cnt[i] : 0;
    sm[t] = v;
    __syncthreads();
    for (int o = 1; o < 1024; o <<= 1) {
        int x = (t >= o) ? sm[t - o] : 0;
        __syncthreads();
        sm[t] += x;
        __syncthreads();
    }
    if (i < NN) g_rowptr[i] = sm[t] - v;     // exclusive
    if (t == 1023) g_bsums[blockIdx.x] = sm[t];
}

__global__ void scan2_k(int nb) {            // exclusive scan of block sums
    __shared__ int sm[128];
    int t = threadIdx.x;
    int v = (t < nb) ? g_bsums[t] : 0;
    sm[t] = v;
    __syncthreads();
    for (int o = 1; o < 128; o <<= 1) {
        int x = (t >= o) ? sm[t - o] : 0;
        __syncthreads();
        sm[t] += x;
        __syncthreads();
    }
    if (t < nb) g_bsums[t] = sm[t] - v;
}

__global__ void scan3_k() {   // add block offsets; also re-zero cnt for fill pass
    int i = blockIdx.x * blockDim.x + threadIdx.x;
    if (i < NN) {
        g_rowptr[i] += g_bsums[i >> 10];
        g_cnt[i] = 0;
    }
    if (i == NN) g_rowptr[NN] = EE;
}

__global__ void fill_k() {
    int j = blockIdx.x * blockDim.x + threadIdx.x;
    if (j >= EE) return;
    int d = g_dst[j];
    int pos = g_rowptr[d] + atomicAdd(&g_cnt[d], 1);
    g_colsrc[pos] = g_src[j];
}

// ---------------------------------------------------------------------------
// Weight pack: Wcat = [W1 | W2] along columns
// ---------------------------------------------------------------------------
__global__ void pack2_k(const float* __restrict__ W1, int C1,
                        const float* __restrict__ W2, int C2, int K) {
    int i = blockIdx.x * blockDim.x + threadIdx.x;
    int Ct = C1 + C2;
    if (i >= K * Ct) return;
    int k = i / Ct, c = i % Ct;
    g_Wcat[i] = (c < C1) ? W1[k * C1 + c] : W2[k * C2 + (c - C1)];
}

// ---------------------------------------------------------------------------
// bf16x3 ("Ootomo split") tensor-core GEMM: C[M,Ncol] = A[M,K=128] @ B[K,Ncol]
// CTA tile 128x128, BK=16, 8 warps (2x4), warp tile 64x32, mma.m16n8k16.bf16.
// hi/lo bf16 split -> ~1e-5 relative accuracy (lo*lo term dropped).
// ---------------------------------------------------------------------------
__device__ __forceinline__ void bf16split2(float x, float y, unsigned& hi, unsigned& lo) {
    __nv_bfloat16 hx = __float2bfloat16_rn(x);
    __nv_bfloat16 hy = __float2bfloat16_rn(y);
    float rx = x - __bfloat162float(hx);
    float ry = y - __bfloat162float(hy);
    __nv_bfloat162 h; h.x = hx; h.y = hy;
    __nv_bfloat162 l; l.x = __float2bfloat16_rn(rx); l.y = __float2bfloat16_rn(ry);
    hi = *reinterpret_cast<unsigned*>(&h);
    lo = *reinterpret_cast<unsigned*>(&l);
}

__device__ __forceinline__ void mma_bf16(float (&d)[4], const unsigned* a, const unsigned* b) {
    asm volatile(
        "mma.sync.aligned.m16n8k16.row.col.f32.bf16.bf16.f32 "
        "{%0,%1,%2,%3}, {%4,%5,%6,%7}, {%8,%9}, {%0,%1,%2,%3};"
        : "+f"(d[0]), "+f"(d[1]), "+f"(d[2]), "+f"(d[3])
        : "r"(a[0]), "r"(a[1]), "r"(a[2]), "r"(a[3]), "r"(b[0]), "r"(b[1]));
}

__global__ __launch_bounds__(256)
void gemm_bf16_k(const float* __restrict__ A, const float* __restrict__ B,
                 float* __restrict__ C, int M, int Ncol) {
    __shared__ unsigned sAh[128][9], sAl[128][9];   // [row][kpair] (kpair = k/2)
    __shared__ unsigned sBh[128][9], sBl[128][9];   // [col][kpair]

    const int bm = blockIdx.x * 128;
    const int bn = blockIdx.y * 128;
    const int tid = threadIdx.x;
    const int lane = tid & 31;
    const int wid = tid >> 5;
    const int warpM = wid >> 2;     // 0..1 -> 64 rows
    const int warpN = wid & 3;      // 0..3 -> 32 cols
    const int g = lane >> 2;        // 0..7
    const int t = lane & 3;         // 0..3

    // A staging: 2 float4 per thread. f4 = tid + i*256: row=f4>>2, colgrp=(f4&3)*4
    const int aR0 = tid >> 2;            // rows for i=0: 0..63  (i=1 adds 64)
    const int aC4 = (tid & 3) * 4;       // k offset 0,4,8,12
    // B staging: kp = tid>>5 (0..7), n4 = (tid&31)*4
    const int bKp = tid >> 5;
    const int bN4 = (tid & 31) * 4;

    float acc[4][4][4];
#pragma unroll
    for (int i = 0; i < 4; i++)
#pragma unroll
        for (int j = 0; j < 4; j++)
#pragma unroll
            for (int q = 0; q < 4; q++) acc[i][j][q] = 0.f;

    float4 rA0, rA1, rB0, rB1;
    // ---- load chunk 0 ----
    {
        const int k0 = 0;
        rA0 = make_float4(0.f, 0.f, 0.f, 0.f);
        rA1 = make_float4(0.f, 0.f, 0.f, 0.f);
        if (bm + aR0 < M)      rA0 = *(const float4*)(A + (size_t)(bm + aR0) * GK + k0 + aC4);
        if (bm + aR0 + 64 < M) rA1 = *(const float4*)(A + (size_t)(bm + aR0 + 64) * GK + k0 + aC4);
        rB0 = *(const float4*)(B + (size_t)(k0 + 2 * bKp) * Ncol + bn + bN4);
        rB1 = *(const float4*)(B + (size_t)(k0 + 2 * bKp + 1) * Ncol + bn + bN4);
    }

#pragma unroll
    for (int kc = 0; kc < 8; kc++) {
        // ---- store staged regs -> smem (with bf16 hi/lo split) ----
        {
            unsigned h0, l0, h1, l1;
            bf16split2(rA0.x, rA0.y, h0, l0);
            bf16split2(rA0.z, rA0.w, h1, l1);
            sAh[aR0][aC4 / 2] = h0; sAh[aR0][aC4 / 2 + 1] = h1;
            sAl[aR0][aC4 / 2] = l0; sAl[aR0][aC4 / 2 + 1] = l1;
            bf16split2(rA1.x, rA1.y, h0, l0);
            bf16split2(rA1.z, rA1.w, h1, l1);
            sAh[aR0 + 64][aC4 / 2] = h0; sAh[aR0 + 64][aC4 / 2 + 1] = h1;
            sAl[aR0 + 64][aC4 / 2] = l0; sAl[aR0 + 64][aC4 / 2 + 1] = l1;

            float u[4] = {rB0.x, rB0.y, rB0.z, rB0.w};
            float w[4] = {rB1.x, rB1.y, rB1.z, rB1.w};
#pragma unroll
            for (int c = 0; c < 4; c++) {
                unsigned h, l;
                bf16split2(u[c], w[c], h, l);   // pack (k even, k odd) for col bN4+c
                sBh[bN4 + c][bKp] = h;
                sBl[bN4 + c][bKp] = l;
            }
        }
        __syncthreads();

        // ---- prefetch next chunk into regs (overlaps with MMAs) ----
        if (kc < 7) {
            const int k0 = (kc + 1) * 16;
            rA0 = make_float4(0.f, 0.f, 0.f, 0.f);
            rA1 = make_float4(0.f, 0.f, 0.f, 0.f);
            if (bm + aR0 < M)      rA0 = *(const float4*)(A + (size_t)(bm + aR0) * GK + k0 + aC4);
            if (bm + aR0 + 64 < M) rA1 = *(const float4*)(A + (size_t)(bm + aR0 + 64) * GK + k0 + aC4);
            rB0 = *(const float4*)(B + (size_t)(k0 + 2 * bKp) * Ncol + bn + bN4);
            rB1 = *(const float4*)(B + (size_t)(k0 + 2 * bKp + 1) * Ncol + bn + bN4);
        }

        // ---- MMAs on current chunk ----
        {
            unsigned ah[4][4], al_[4][4], bh[4][2], bl[4][2];
#pragma unroll
            for (int mf = 0; mf < 4; mf++) {
                int r = warpM * 64 + mf * 16 + g;
                ah[mf][0] = sAh[r][t];       al_[mf][0] = sAl[r][t];
                ah[mf][1] = sAh[r + 8][t];   al_[mf][1] = sAl[r + 8][t];
                ah[mf][2] = sAh[r][t + 4];   al_[mf][2] = sAl[r][t + 4];
                ah[mf][3] = sAh[r + 8][t + 4]; al_[mf][3] = sAl[r + 8][t + 4];
            }
#pragma unroll
            for (int nf = 0; nf < 4; nf++) {
                int n = warpN * 32 + nf * 8 + g;
                bh[nf][0] = sBh[n][t];     bl[nf][0] = sBl[n][t];
                bh[nf][1] = sBh[n][t + 4]; bl[nf][1] = sBl[n][t + 4];
            }
#pragma unroll
            for (int mf = 0; mf < 4; mf++)
#pragma unroll
                for (int nf = 0; nf < 4; nf++) {
                    mma_bf16(acc[mf][nf], al_[mf], bh[nf]);
                    mma_bf16(acc[mf][nf], ah[mf], bl[nf]);
                    mma_bf16(acc[mf][nf], ah[mf], bh[nf]);
                }
        }
        __syncthreads();
    }

    // ---- epilogue ----
#pragma unroll
    for (int mf = 0; mf < 4; mf++) {
        int r0 = bm + warpM * 64 + mf * 16 + g;
#pragma unroll
        for (int nf = 0; nf < 4; nf++) {
            int c = bn + warpN * 32 + nf * 8 + 2 * t;
            if (r0 < M)
                *(float2*)(C + (size_t)r0 * Ncol + c) = make_float2(acc[mf][nf][0], acc[mf][nf][1]);
            if (r0 + 8 < M)
                *(float2*)(C + (size_t)(r0 + 8) * Ncol + c) = make_float2(acc[mf][nf][2], acc[mf][nf][3]);
        }
    }
}

// ---------------------------------------------------------------------------
// Per-node attention logits, C=128 (float4 per lane)
// ---------------------------------------------------------------------------
__global__ void al128_k(const float* __restrict__ h, int ldh,
                        const float* __restrict__ a_s, const float* __restrict__ a_d) {
    int n = (blockIdx.x * blockDim.x + threadIdx.x) >> 5;
    int lane = threadIdx.x & 31;
    if (n >= NN) return;
    float4 v = *(const float4*)(h + (size_t)n * ldh + lane * 4);
    float4 as4 = *(const float4*)(a_s + lane * 4);
    float4 ad4 = *(const float4*)(a_d + lane * 4);
    float ss = v.x * as4.x + v.y * as4.y + v.z * as4.z + v.w * as4.w;
    float dd = v.x * ad4.x + v.y * ad4.y + v.z * ad4.z + v.w * ad4.w;
    for (int o = 16; o; o >>= 1) {
        ss += __shfl_xor_sync(0xffffffffu, ss, o);
        dd += __shfl_xor_sync(0xffffffffu, dd, o);
    }
    if (lane == 0) { g_als[n] = ss; g_ald[n] = dd; }
}

// Heads: mu uses cols 0..63, lv uses cols 64..127 of lin (ld 128).
__global__ void al_heads_k(const float* __restrict__ h,
                           const float* __restrict__ a_smu, const float* __restrict__ a_dmu,
                           const float* __restrict__ a_slv, const float* __restrict__ a_dlv) {
    int n = (blockIdx.x * blockDim.x + threadIdx.x) >> 5;
    int lane = threadIdx.x & 31;
    if (n >= NN) return;
    float4 v = *(const float4*)(h + (size_t)n * 128 + lane * 4);
    float4 as4, ad4;
    if (lane < 16) {
        as4 = *(const float4*)(a_smu + lane * 4);
        ad4 = *(const float4*)(a_dmu + lane * 4);
    } else {
        as4 = *(const float4*)(a_slv + (lane - 16) * 4);
        ad4 = *(const float4*)(a_dlv + (lane - 16) * 4);
    }
    float ss = v.x * as4.x + v.y * as4.y + v.z * as4.z + v.w * as4.w;
    float dd = v.x * ad4.x + v.y * ad4.y + v.z * ad4.z + v.w * ad4.w;
    for (int o = 8; o; o >>= 1) {   // reduce within each 16-lane half
        ss += __shfl_xor_sync(0xffffffffu, ss, o);
        dd += __shfl_xor_sync(0xffffffffu, dd, o);
    }
    if (lane == 0)  { g_als[n]  = ss; g_ald[n]  = dd; }
    if (lane == 16) { g_als2[n] = ss; g_ald2[n] = dd; }
}

// ---------------------------------------------------------------------------
// Layer aggregation + fused combine:
// feat[n] = LeakyReLU( softmax-agg(h_gat) + b + h_self + slb, 0.01 )
// h layout: [N,256], gat part cols 0..127, self-linear cols 128..255.
// ---------------------------------------------------------------------------
__global__ void agg_layer_k(const float* __restrict__ h,
                            const float* __restrict__ b, const float* __restrict__ slb,
                            float* __restrict__ outf, int addSelf) {
    int n = (blockIdx.x * blockDim.x + threadIdx.x) >> 5;
    int lane = threadIdx.x & 31;
    if (n >= NN) return;
    int beg = g_rowptr[n], end = g_rowptr[n + 1];
    float aldn = g_ald[n];

    float m = addSelf ? lrelu02(g_als[n] + aldn) : -1e30f;
    for (int j = beg + lane; j < end; j += 32)
        m = fmaxf(m, lrelu02(g_als[g_colsrc[j]] + aldn));
    for (int o = 16; o; o >>= 1) m = fmaxf(m, __shfl_xor_sync(0xffffffffu, m, o));

    float s = 0.f;
    float a0 = 0.f, a1 = 0.f, a2 = 0.f, a3 = 0.f;
    const int co = lane << 2;
    for (int j = beg; j < end; ++j) {
        int sj = g_colsrc[j];
        float w = __expf(lrelu02(g_als[sj] + aldn) - m);
        s += w;
        float4 v = *(const float4*)(h + (size_t)sj * 256 + co);
        a0 = fmaf(w, v.x, a0); a1 = fmaf(w, v.y, a1);
        a2 = fmaf(w, v.z, a2); a3 = fmaf(w, v.w, a3);
    }
    if (addSelf) {
        float w = __expf(lrelu02(g_als[n] + aldn) - m);
        s += w;
        float4 v = *(const float4*)(h + (size_t)n * 256 + co);
        a0 = fmaf(w, v.x, a0); a1 = fmaf(w, v.y, a1);
        a2 = fmaf(w, v.z, a2); a3 = fmaf(w, v.w, a3);
    }
    float inv = 1.f / (s + 1e-16f);
    float4 bb  = *(const float4*)(b + co);
    float4 sb  = *(const float4*)(slb + co);
    float4 sl  = *(const float4*)(h + (size_t)n * 256 + 128 + co);
    float4 r;
    r.x = a0 * inv + bb.x + sl.x + sb.x;
    r.y = a1 * inv + bb.y + sl.y + sb.y;
    r.z = a2 * inv + bb.z + sl.z + sb.z;
    r.w = a3 * inv + bb.w + sl.w + sb.w;
    r.x = r.x > 0.f ? r.x : 0.01f * r.x;
    r.y = r.y > 0.f ? r.y : 0.01f * r.y;
    r.z = r.z > 0.f ? r.z : 0.01f * r.z;
    r.w = r.w > 0.f ? r.w : 0.01f * r.w;
    *(float4*)(outf + (size_t)n * 128 + co) = r;
}

// ---------------------------------------------------------------------------
// Heads aggregation (mu + logvar in one pass). h: [N,128] (mu cols 0..63, lv 64..127).
// Lanes 0..15 -> mu channels, 16..31 -> lv. Self loops always on.
// ---------------------------------------------------------------------------
__global__ void agg_heads_k(const float* __restrict__ h,
                            const float* __restrict__ b_mu, const float* __restrict__ b_lv,
                            float* __restrict__ out) {
    int n = (blockIdx.x * blockDim.x + threadIdx.x) >> 5;
    int lane = threadIdx.x & 31;
    if (n >= NN) return;
    int beg = g_rowptr[n], end = g_rowptr[n + 1];
    float aldmu = g_ald[n], aldlv = g_ald2[n];

    float mmu = lrelu02(g_als[n] + aldmu);     // self term
    float mlv = lrelu02(g_als2[n] + aldlv);
    for (int j = beg + lane; j < end; j += 32) {
        int sj = g_colsrc[j];
        mmu = fmaxf(mmu, lrelu02(g_als[sj] + aldmu));
        mlv = fmaxf(mlv, lrelu02(g_als2[sj] + aldlv));
    }
    for (int o = 16; o; o >>= 1) {
        mmu = fmaxf(mmu, __shfl_xor_sync(0xffffffffu, mmu, o));
        mlv = fmaxf(mlv, __shfl_xor_sync(0xffffffffu, mlv, o));
    }
    const bool isMu = lane < 16;
    const float msel = isMu ? mmu : mlv;

    float s = 0.f;
    float a0 = 0.f, a1 = 0.f, a2 = 0.f, a3 = 0.f;
    const int co = lane << 2;
    for (int j = beg; j < end; ++j) {
        int sj = g_colsrc[j];
        float e = isMu ? lrelu02(g_als[sj] + aldmu) : lrelu02(g_als2[sj] + aldlv);
        float w = __expf(e - msel);
        s += w;
        float4 v = *(const float4*)(h + (size_t)sj * 128 + co);
        a0 = fmaf(w, v.x, a0); a1 = fmaf(w, v.y, a1);
        a2 = fmaf(w, v.z, a2); a3 = fmaf(w, v.w, a3);
    }
    {   // self loop
        float e = isMu ? lrelu02(g_als[n] + aldmu) : lrelu02(g_als2[n] + aldlv);
        float w = __expf(e - msel);
        s += w;
        float4 v = *(const float4*)(h + (size_t)n * 128 + co);
        a0 = fmaf(w, v.x, a0); a1 = fmaf(w, v.y, a1);
        a2 = fmaf(w, v.z, a2); a3 = fmaf(w, v.w, a3);
    }
    float inv = 1.f / (s + 1e-16f);
    if (isMu) {
        float4 bb = *(const float4*)(b_mu + co);
        float4 r = make_float4(a0 * inv + bb.x, a1 * inv + bb.y,
                               a2 * inv + bb.z, a3 * inv + bb.w);
        *(float4*)(out + (size_t)n * 64 + co) = r;
    } else {
        int c2 = (lane - 16) << 2;
        float4 bb = *(const float4*)(b_lv + c2);
        float4 r = make_float4(a0 * inv + bb.x, a1 * inv + bb.y,
                               a2 * inv + bb.z, a3 * inv + bb.w);
        *(float4*)(out + (size_t)NN * 64 + (size_t)n * 64 + c2) = r;
    }
}

// ---------------------------------------------------------------------------
// Launch
// ---------------------------------------------------------------------------
extern "C" void kernel_launch(void* const* d_in, const int* in_sizes, int n_in,
                              void* d_out, int out_size) {
    const float* x      = (const float*)d_in[0];
    const void*  edge   = d_in[1];
    const float* W0     = (const float*)d_in[2];
    const float* a_src0 = (const float*)d_in[3];
    const float* a_dst0 = (const float*)d_in[4];
    const float* b0     = (const float*)d_in[5];
    const float* slW0   = (const float*)d_in[6];
    const float* slb0   = (const float*)d_in[7];
    const float* W1     = (const float*)d_in[8];
    const float* a_src1 = (const float*)d_in[9];
    const float* a_dst1 = (const float*)d_in[10];
    const float* b1     = (const float*)d_in[11];
    const float* slW1   = (const float*)d_in[12];
    const float* slb1   = (const float*)d_in[13];
    const float* Wmu    = (const float*)d_in[14];
    const float* a_smu  = (const float*)d_in[15];
    const float* a_dmu  = (const float*)d_in[16];
    const float* b_mu   = (const float*)d_in[17];
    const float* Wlv    = (const float*)d_in[18];
    const float* a_slv  = (const float*)d_in[19];
    const float* a_dlv  = (const float*)d_in[20];
    const float* b_lv   = (const float*)d_in[21];
    float* out = (float*)d_out;

    float* lin;  cudaGetSymbolAddress((void**)&lin,  g_lin);
    float* feat; cudaGetSymbolAddress((void**)&feat, g_feat);
    float* feat2;cudaGetSymbolAddress((void**)&feat2,g_feat2);
    float* Wcat; cudaGetSymbolAddress((void**)&Wcat, g_Wcat);

    const int TB = 256;
    const int egrid = (EE + TB - 1) / TB;
    const int ngrid = (NN + TB - 1) / TB;
    const int nb = (NN + 1023) / 1024;
    const int warpsGrid = (NN * 32 + TB - 1) / TB;   // warp per node

    // --- edges -> int32, degree count, CSR ---
    zero_cnt_k<<<ngrid, TB>>>();
    detect_k<<<1, 256>>>((const unsigned*)edge);
    convert_count_k<<<egrid, TB>>>(edge);
    scan1_k<<<nb, 1024>>>();
    scan2_k<<<1, 128>>>(nb);
    scan3_k<<<(NN + 1 + TB - 1) / TB, TB>>>();   // also re-zeros cnt
    fill_k<<<egrid, TB>>>();

    // ===================== layer 0 =====================
    pack2_k<<<(FH * 256 + TB - 1) / TB, TB>>>(W0, FH, slW0, FH, FH);
    {
        dim3 grid((NN + 127) / 128, 2);
        gemm_bf16_k<<<grid, 256>>>(x, Wcat, lin, NN, 256);
    }
    al128_k<<<warpsGrid, TB>>>(lin, 256, a_src0, a_dst0);
    agg_layer_k<<<warpsGrid, TB>>>(lin, b0, slb0, feat, 0);

    // ===================== layer 1 =====================
    pack2_k<<<(FH * 256 + TB - 1) / TB, TB>>>(W1, FH, slW1, FH, FH);
    {
        dim3 grid((NN + 127) / 128, 2);
        gemm_bf16_k<<<grid, 256>>>(feat, Wcat, lin, NN, 256);
    }
    al128_k<<<warpsGrid, TB>>>(lin, 256, a_src1, a_dst1);
    agg_layer_k<<<warpsGrid, TB>>>(lin, b1, slb1, feat2, 1);

    // ===================== heads (mu | logvar) =====================
    pack2_k<<<(FH * 128 + TB - 1) / TB, TB>>>(Wmu, LATC, Wlv, LATC, FH);
    {
        dim3 grid((NN + 127) / 128, 1);
        gemm_bf16_k<<<grid, 256>>>(feat2, Wcat, lin, NN, 128);
    }
    al_heads_k<<<warpsGrid, TB>>>(lin, a_smu, a_dmu, a_slv, a_dlv);
    agg_heads_k<<<warpsGrid, TB>>>(lin, b_mu, b_lv, out);
}